// round 5
// baseline (speedup 1.0000x reference)
#include <cuda_runtime.h>
#include <math.h>
#include <cstdint>

#define BB 32
#define NN 1024
#define IND 64
#define ATTN 128
#define OUTD 64
#define CTOT 320   // Q(128) | K(128) | V(64)

// ---------------- scratch (device globals; no allocations allowed) ----------
__device__ float g_deg[BB * NN];
__device__ float g_diag[BB * NN];
__device__ float g_H[(size_t)BB * NN * CTOT];   // d-prescaled x@W, tf32-rounded
__device__ float g_Q[(size_t)BB * NN * ATTN];   // tf32-rounded
__device__ float g_K[(size_t)BB * NN * ATTN];   // tf32-rounded

// ---------------- tf32 MMA helpers -----------------------------------------
__device__ __forceinline__ uint32_t f2tf32(float x) {
    uint32_t r;
    asm("cvt.rna.tf32.f32 %0, %1;" : "=r"(r) : "f"(x));
    return r;
}
__device__ __forceinline__ float f2tf32f(float x) {
    return __uint_as_float(f2tf32(x));
}

__device__ __forceinline__ void mma_tf32(float c[4],
                                         uint32_t a0, uint32_t a1, uint32_t a2, uint32_t a3,
                                         uint32_t b0, uint32_t b1) {
    asm volatile(
        "mma.sync.aligned.m16n8k8.row.col.f32.tf32.tf32.f32 "
        "{%0,%1,%2,%3}, {%4,%5,%6,%7}, {%8,%9}, {%0,%1,%2,%3};\n"
        : "+f"(c[0]), "+f"(c[1]), "+f"(c[2]), "+f"(c[3])
        : "r"(a0), "r"(a1), "r"(a2), "r"(a3), "r"(b0), "r"(b1));
}

// fast accurate tanh: (e^{2x}-1)/(e^{2x}+1) via MUFU; ~1e-6 rel err
__device__ __forceinline__ float fast_tanh(float x) {
    float a = fminf(x * 2.885390082f, 126.0f);
    float e;
    asm("ex2.approx.f32 %0, %1;" : "=f"(e) : "f"(a));
    float r;
    asm("rcp.approx.f32 %0, %1;" : "=f"(r) : "f"(e + 1.0f));
    return (e - 1.0f) * r;
}

// ---------------- kernel A: row degrees + diagonal --------------------------
__global__ void __launch_bounds__(256) deg_kernel(const float* __restrict__ adj) {
    int warp = (blockIdx.x * blockDim.x + threadIdx.x) >> 5;
    int lane = threadIdx.x & 31;
    if (warp >= BB * NN) return;
    const float* row = adj + (size_t)warp * NN;
    const float4* r4 = (const float4*)row;
    float s = 0.f;
#pragma unroll
    for (int j = lane; j < NN / 4; j += 32) {
        float4 v = r4[j];
        s += (v.x + v.y) + (v.z + v.w);
    }
#pragma unroll
    for (int o = 16; o; o >>= 1) s += __shfl_xor_sync(0xffffffffu, s, o);
    if (lane == 0) {
        int i = warp & (NN - 1);
        float dg = row[i];
        float rs = s - dg + 1.0f;
        g_deg[warp]  = rsqrtf(fmaxf(rs, 1.0f));
        g_diag[warp] = dg;
    }
}

// ---------------- kernel B: H' = tf32(diag(d) * (x @ [Wq|Wk|Wv])) ------------
__global__ void __launch_bounds__(320) h_kernel(const float* __restrict__ x,
                                                const float* __restrict__ Wq,
                                                const float* __restrict__ Wk,
                                                const float* __restrict__ Wv) {
    __shared__ float xs[64][IND];
    int b = blockIdx.y;
    int rb = blockIdx.x;
    int t = threadIdx.x;
    size_t rowbase = ((size_t)b * NN + rb * 64);

    for (int idx = t; idx < 64 * IND; idx += 320) {
        int r = idx >> 6, k = idx & 63;
        xs[r][k] = x[(rowbase + r) * IND + k];
    }
    __syncthreads();

    const float* Wcol;
    int stride;
    if (t < 128)      { Wcol = Wq + t;          stride = 128; }
    else if (t < 256) { Wcol = Wk + (t - 128);  stride = 128; }
    else              { Wcol = Wv + (t - 256);  stride = 64;  }

    float w[64];
#pragma unroll
    for (int k = 0; k < 64; k++) w[k] = Wcol[(size_t)k * stride];

    const float4* xs4 = (const float4*)&xs[0][0];
    for (int r = 0; r < 64; r++) {
        float acc = 0.f;
#pragma unroll
        for (int kq = 0; kq < 16; kq++) {
            float4 xv = xs4[r * 16 + kq];
            acc += xv.x * w[kq * 4 + 0];
            acc += xv.y * w[kq * 4 + 1];
            acc += xv.z * w[kq * 4 + 2];
            acc += xv.w * w[kq * 4 + 3];
        }
        g_H[(rowbase + r) * CTOT + t] = f2tf32f(g_deg[rowbase + r] * acc);
    }
}

// ---------------- kernel C: tf32 tensor-core GCN GEMM (fragment-major smem) -
// C = diag(d) * (adj_raw @ H' + (1-diag)*H'_row) + bias, routed to Q/K/V.
// CTA tile 128(M) x 64(N), K step 32. 8 warps in 4(m) x 2(n); warp = 32x32.
__global__ void __launch_bounds__(256) gcn_gemm_tc(const float* __restrict__ adj,
                                                   const float* __restrict__ bq,
                                                   const float* __restrict__ bk,
                                                   const float* __restrict__ bv,
                                                   float* __restrict__ outV) {
    __shared__ float As[8 * 4 * 32 * 4];   // 16 KB (128 rows x 32 k, frag-major)
    __shared__ float Bs[8 * 4 * 32 * 2];   //  8 KB (32 k x 64 cols, frag-major)

    int b  = blockIdx.z;
    int mt = blockIdx.y;     // 0..7 -> 128-row tiles
    int cb = blockIdx.x;     // 0..4 -> 64-col tiles of 320
    int t  = threadIdx.x;
    int wid = t >> 5, lane = t & 31;
    int g = lane >> 2, tg = lane & 3;
    int wm = wid >> 1, wn = wid & 1;

    const float* adjb = adj + (size_t)b * NN * NN + (size_t)(mt * 128) * NN;
    const float* Hb   = g_H + (size_t)b * NN * CTOT;
    int colbase = cb * 64;

    // staging coordinates (fixed per thread)
    int ar[4], aq[4];
#pragma unroll
    for (int i = 0; i < 4; i++) { int lin = t + i * 256; ar[i] = lin >> 3; aq[i] = lin & 7; }
    int bkk[2], bq_[2];
#pragma unroll
    for (int i = 0; i < 2; i++) { int lin = t + i * 256; bkk[i] = lin >> 4; bq_[i] = lin & 15; }

    // precomputed frag-store bases
    int abase[4];
#pragma unroll
    for (int i = 0; i < 4; i++) {
        int r = ar[i], q = aq[i];
        int rb = r >> 4, rbit = (r >> 3) & 1, gg = r & 7;
        int ks = q >> 1, hi = q & 1;
        abase[i] = ((rb * 4 + ks) * 32 + gg * 4) * 4 + rbit + 2 * hi;
    }
    int bbase[2];
#pragma unroll
    for (int i = 0; i < 2; i++) {
        int kk = bkk[i], q = bq_[i];
        int ks = kk >> 3, tgk = kk & 3, hi = (kk >> 2) & 1;
        int nb = q >> 1;
        bbase[i] = ((nb * 4 + ks) * 32 + (q & 1) * 16 + tgk) * 2 + hi;
    }

    float4 pa[4], pb[2];
#define LOAD_PREF(K0)                                                              \
    {                                                                              \
        _Pragma("unroll")                                                          \
        for (int i = 0; i < 4; i++)                                                \
            pa[i] = *(const float4*)(adjb + (size_t)ar[i] * NN + (K0) + aq[i] * 4);\
        _Pragma("unroll")                                                          \
        for (int i = 0; i < 2; i++)                                                \
            pb[i] = *(const float4*)(Hb + (size_t)((K0) + bkk[i]) * CTOT + colbase + bq_[i] * 4); \
    }
#define STORE_SMEM()                                                               \
    {                                                                              \
        _Pragma("unroll")                                                          \
        for (int i = 0; i < 4; i++) {                                              \
            As[abase[i] + 0]  = f2tf32f(pa[i].x);                                  \
            As[abase[i] + 4]  = f2tf32f(pa[i].y);                                  \
            As[abase[i] + 8]  = f2tf32f(pa[i].z);                                  \
            As[abase[i] + 12] = f2tf32f(pa[i].w);                                  \
        }                                                                          \
        _Pragma("unroll")                                                          \
        for (int i = 0; i < 2; i++) {                                              \
            Bs[bbase[i] + 0]  = pb[i].x;                                           \
            Bs[bbase[i] + 8]  = pb[i].y;                                           \
            Bs[bbase[i] + 16] = pb[i].z;                                           \
            Bs[bbase[i] + 24] = pb[i].w;                                           \
        }                                                                          \
    }

    float acc[2][4][4];
#pragma unroll
    for (int m = 0; m < 2; m++)
#pragma unroll
        for (int n = 0; n < 4; n++)
#pragma unroll
            for (int e = 0; e < 4; e++) acc[m][n][e] = 0.f;

    LOAD_PREF(0);
    STORE_SMEM();

    for (int k0 = 0; k0 < NN; k0 += 32) {
        __syncthreads();
        if (k0 + 32 < NN) LOAD_PREF(k0 + 32);

#pragma unroll
        for (int ks = 0; ks < 4; ks++) {
            float4 a4[2];
#pragma unroll
            for (int m = 0; m < 2; m++)
                a4[m] = *(const float4*)&As[(((wm * 2 + m) * 4 + ks) * 32 + lane) * 4];
#pragma unroll
            for (int n = 0; n < 4; n++) {
                int nb = wn * 4 + n;
                float2 b2 = *(const float2*)&Bs[((nb * 4 + ks) * 32 + lane) * 2];
                uint32_t b0 = __float_as_uint(b2.x), b1 = __float_as_uint(b2.y);
#pragma unroll
                for (int m = 0; m < 2; m++)
                    mma_tf32(acc[m][n],
                             __float_as_uint(a4[m].x), __float_as_uint(a4[m].y),
                             __float_as_uint(a4[m].z), __float_as_uint(a4[m].w),
                             b0, b1);
            }
        }
        __syncthreads();
        if (k0 + 32 < NN) STORE_SMEM();
    }

    // epilogue: route to g_Q / g_K / outV; round Q/K to tf32 for the attn pass
    float* dst; const float* barr; int jb, stride; bool roundout;
    if (cb < 2)      { dst = g_Q + (size_t)b * NN * ATTN;  barr = bq; jb = cb * 64;       stride = ATTN; roundout = true; }
    else if (cb < 4) { dst = g_K + (size_t)b * NN * ATTN;  barr = bk; jb = (cb - 2) * 64; stride = ATTN; roundout = true; }
    else             { dst = outV + (size_t)b * NN * OUTD; barr = bv; jb = 0;             stride = OUTD; roundout = false; }

#pragma unroll
    for (int m = 0; m < 2; m++) {
        int r0 = mt * 128 + wm * 32 + m * 16 + g;
#pragma unroll
        for (int rr = 0; rr < 2; rr++) {
            int i = r0 + rr * 8;
            size_t gi = (size_t)b * NN + i;
            float d    = g_deg[gi];
            float corr = 1.0f - g_diag[gi];
#pragma unroll
            for (int n = 0; n < 4; n++) {
                int jl = jb + wn * 32 + n * 8 + 2 * tg;
                int jg = colbase + wn * 32 + n * 8 + 2 * tg;
                float2 h2 = *(const float2*)(Hb + (size_t)i * CTOT + jg);
                float v0 = d * (acc[m][n][rr * 2 + 0] + corr * h2.x) + barr[jl];
                float v1 = d * (acc[m][n][rr * 2 + 1] + corr * h2.y) + barr[jl + 1];
                if (roundout) { v0 = f2tf32f(v0); v1 = f2tf32f(v1); }
                float2 ov; ov.x = v0; ov.y = v1;
                *(float2*)(dst + (size_t)i * stride + jl) = ov;
            }
        }
    }
}

// ---------------- kernel D: tensor-core A = sym(mean_h tanh(Qh Khᵀ / 8)) ----
#define TS 65

// stage 64x128 tile (row-major, ld=ATTN) into A-fragment layout
__device__ __forceinline__ void stage_a64(float* dst, const float* __restrict__ src, int t) {
    for (int idx = t; idx < 64 * 32; idx += 256) {
        int r = idx >> 5, q = idx & 31;
        float4 v = *(const float4*)(src + r * ATTN + q * 4);
        int rb = r >> 4, rbit = (r >> 3) & 1, g = r & 7;
        int ks = q >> 1, hi = q & 1;
        float* base = dst + ((rb * 16 + ks) * 32 + g * 4) * 4 + rbit + 2 * hi;
        base[0]  = v.x;
        base[4]  = v.y;
        base[8]  = v.z;
        base[12] = v.w;
    }
}

// stage 64x128 tile into B-fragment layout (rows are the N/col dimension)
__device__ __forceinline__ void stage_b64(float* dst, const float* __restrict__ src, int t) {
    for (int idx = t; idx < 64 * 32; idx += 256) {
        int c = idx >> 5, q = idx & 31;
        float4 v = *(const float4*)(src + c * ATTN + q * 4);
        int nb = c >> 3, g = c & 7;
        int ks = q >> 1, hi = q & 1;
        float* base = dst + ((nb * 16 + ks) * 32 + g * 4) * 2 + hi;
        base[0] = v.x;
        base[2] = v.y;
        base[4] = v.z;
        base[6] = v.w;
    }
}

// warp layout: 8 warps = 4(m) x 2(n); warp = 16 rows x 32 cols.
__device__ __forceinline__ void attn_compute(const float* __restrict__ Qf,
                                             const float* __restrict__ Kf,
                                             int wm, int wn, int lane,
                                             float out[4][4]) {
#pragma unroll
    for (int n = 0; n < 4; n++)
#pragma unroll
        for (int e = 0; e < 4; e++) out[n][e] = 0.f;

#pragma unroll
    for (int h = 0; h < 4; h++) {
        float acc[4][4];
#pragma unroll
        for (int n = 0; n < 4; n++)
#pragma unroll
            for (int e = 0; e < 4; e++) acc[n][e] = 0.f;

#pragma unroll
        for (int ks = 0; ks < 4; ks++) {
            int kg = h * 4 + ks;
            float4 a4 = *(const float4*)&Qf[((wm * 16 + kg) * 32 + lane) * 4];
            uint32_t a0 = __float_as_uint(a4.x), a1 = __float_as_uint(a4.y);
            uint32_t a2 = __float_as_uint(a4.z), a3 = __float_as_uint(a4.w);
#pragma unroll
            for (int n = 0; n < 4; n++) {
                int nb = wn * 4 + n;
                float2 b2 = *(const float2*)&Kf[((nb * 16 + kg) * 32 + lane) * 2];
                mma_tf32(acc[n], a0, a1, a2, a3,
                         __float_as_uint(b2.x), __float_as_uint(b2.y));
            }
        }
#pragma unroll
        for (int n = 0; n < 4; n++)
#pragma unroll
            for (int e = 0; e < 4; e++)
                out[n][e] += fast_tanh(acc[n][e] * 0.125f);
    }
#pragma unroll
    for (int n = 0; n < 4; n++)
#pragma unroll
        for (int e = 0; e < 4; e++) out[n][e] *= 0.25f;
}

#define QFSZ (64 * 128)
#define SMEM_D ((2 * QFSZ + 2 * 64 * TS) * (int)sizeof(float))  // 98,560 B

__global__ void __launch_bounds__(256) attn_tc(float* __restrict__ outA) {
    extern __shared__ float sm[];
    float* Qf = sm;
    float* Kf = sm + QFSZ;
    float* T1 = sm + 2 * QFSZ;
    float* C2 = T1 + 64 * TS;

    int I = blockIdx.x, J = blockIdx.y, b = blockIdx.z;
    if (J < I) return;
    int t = threadIdx.x;
    int wid = t >> 5, lane = t & 31;
    int g = lane >> 2, tg = lane & 3;
    int wm = wid >> 1, wn = wid & 1;

    stage_a64(Qf, g_Q + ((size_t)b * NN + I * 64) * ATTN, t);
    stage_b64(Kf, g_K + ((size_t)b * NN + J * 64) * ATTN, t);
    __syncthreads();

    float o1[4][4];
    attn_compute(Qf, Kf, wm, wn, lane, o1);   // raw tile (I,J)
#pragma unroll
    for (int n = 0; n < 4; n++)
#pragma unroll
        for (int e = 0; e < 4; e++) {
            int r = wm * 16 + g + (e >> 1) * 8;
            int c = wn * 32 + n * 8 + 2 * tg + (e & 1);
            T1[r * TS + c] = o1[n][e];
        }
    __syncthreads();

    if (I == J) {
        for (int idx = t; idx < 4096; idx += 256) {
            int r = idx >> 6, c = idx & 63;
            C2[r * TS + c] = 0.5f * (T1[r * TS + c] + T1[c * TS + r]);
        }
        __syncthreads();
    } else {
        stage_a64(Qf, g_Q + ((size_t)b * NN + J * 64) * ATTN, t);
        stage_b64(Kf, g_K + ((size_t)b * NN + I * 64) * ATTN, t);
        __syncthreads();
        float o2[4][4];
        attn_compute(Qf, Kf, wm, wn, lane, o2);  // raw tile (J,I)
#pragma unroll
        for (int n = 0; n < 4; n++)
#pragma unroll
            for (int e = 0; e < 4; e++) {
                int r = wm * 16 + g + (e >> 1) * 8;
                int c = wn * 32 + n * 8 + 2 * tg + (e & 1);
                C2[r * TS + c] = 0.5f * (o2[n][e] + T1[c * TS + r]);
            }
        __syncthreads();
    }

    // C2 holds output tile (J,I): scalar LDS reads (TS=65 breaks 16B alignment),
    // packed STG.128 global writes.
    float* ob = outA + ((size_t)b * NN + J * 64) * NN + I * 64;
    for (int idx = t; idx < 1024; idx += 256) {
        int r = idx >> 4, cq = idx & 15;
        const float* row = &C2[r * TS + cq * 4];
        float4 v;
        v.x = row[0]; v.y = row[1]; v.z = row[2]; v.w = row[3];
        *(float4*)(ob + (size_t)r * NN + cq * 4) = v;
    }
    if (I != J) {
        float* ob2 = outA + ((size_t)b * NN + I * 64) * NN + J * 64;
        for (int idx = t; idx < 1024; idx += 256) {
            int r = idx >> 4, cq = idx & 15;
            float4 v;
            v.x = C2[(cq * 4 + 0) * TS + r];
            v.y = C2[(cq * 4 + 1) * TS + r];
            v.z = C2[(cq * 4 + 2) * TS + r];
            v.w = C2[(cq * 4 + 3) * TS + r];
            *(float4*)(ob2 + (size_t)r * NN + cq * 4) = v;
        }
    }
}

// ---------------- launch -----------------------------------------------------
extern "C" void kernel_launch(void* const* d_in, const int* in_sizes, int n_in,
                              void* d_out, int out_size) {
    (void)in_sizes; (void)n_in; (void)out_size;
    const float* x   = (const float*)d_in[0];
    const float* adj = (const float*)d_in[1];
    // d_in[2] = flags (unused by reference)
    const float* Wq = (const float*)d_in[3];
    const float* bq = (const float*)d_in[4];
    const float* Wk = (const float*)d_in[5];
    const float* bk = (const float*)d_in[6];
    const float* Wv = (const float*)d_in[7];
    const float* bv = (const float*)d_in[8];

    float* outV = (float*)d_out;                            // [B,N,64]
    float* outA = (float*)d_out + (size_t)BB * NN * OUTD;   // [B,N,N]

    cudaFuncSetAttribute(attn_tc,
                         cudaFuncAttributeMaxDynamicSharedMemorySize, SMEM_D);

    deg_kernel<<<(BB * NN) / 8, 256>>>(adj);
    h_kernel<<<dim3(16, BB), 320>>>(x, Wq, Wk, Wv);
    gcn_gemm_tc<<<dim3(5, 8, BB), 256>>>(adj, bq, bk, bv, outV);
    attn_tc<<<dim3(16, 16, BB), 256, SMEM_D>>>(outA);
}

// round 6
// speedup vs baseline: 2.0433x; 2.0433x over previous
#include <cuda_runtime.h>
#include <math.h>
#include <cstdint>

#define BB 32
#define NN 1024
#define IND 64
#define ATTN 128
#define OUTD 64
#define CTOT 320   // Q(128) | K(128) | V(64)

// ---------------- scratch (device globals; no allocations allowed) ----------
__device__ float g_deg[BB * NN];
__device__ float g_diag[BB * NN];
__device__ float g_H[(size_t)BB * NN * CTOT];   // d-prescaled x@W, tf32-rounded
__device__ float g_Q[(size_t)BB * NN * ATTN];   // tf32-rounded
__device__ float g_K[(size_t)BB * NN * ATTN];   // tf32-rounded

// ---------------- tf32 MMA helpers -----------------------------------------
__device__ __forceinline__ uint32_t f2tf32(float x) {
    uint32_t r;
    asm("cvt.rna.tf32.f32 %0, %1;" : "=r"(r) : "f"(x));
    return r;
}
__device__ __forceinline__ float f2tf32f(float x) {
    return __uint_as_float(f2tf32(x));
}

__device__ __forceinline__ void mma_tf32(float c[4],
                                         uint32_t a0, uint32_t a1, uint32_t a2, uint32_t a3,
                                         uint32_t b0, uint32_t b1) {
    asm volatile(
        "mma.sync.aligned.m16n8k8.row.col.f32.tf32.tf32.f32 "
        "{%0,%1,%2,%3}, {%4,%5,%6,%7}, {%8,%9}, {%0,%1,%2,%3};\n"
        : "+f"(c[0]), "+f"(c[1]), "+f"(c[2]), "+f"(c[3])
        : "r"(a0), "r"(a1), "r"(a2), "r"(a3), "r"(b0), "r"(b1));
}

// fast accurate tanh: (e^{2x}-1)/(e^{2x}+1) via MUFU; ~1e-6 rel err
__device__ __forceinline__ float fast_tanh(float x) {
    float a = fminf(x * 2.885390082f, 126.0f);
    float e;
    asm("ex2.approx.f32 %0, %1;" : "=f"(e) : "f"(a));
    float r;
    asm("rcp.approx.f32 %0, %1;" : "=f"(r) : "f"(e + 1.0f));
    return (e - 1.0f) * r;
}

// ---------------- kernel A: row degrees + diagonal --------------------------
__global__ void __launch_bounds__(256) deg_kernel(const float* __restrict__ adj) {
    int warp = (blockIdx.x * blockDim.x + threadIdx.x) >> 5;
    int lane = threadIdx.x & 31;
    if (warp >= BB * NN) return;
    const float* row = adj + (size_t)warp * NN;
    const float4* r4 = (const float4*)row;
    float s = 0.f;
#pragma unroll
    for (int j = lane; j < NN / 4; j += 32) {
        float4 v = r4[j];
        s += (v.x + v.y) + (v.z + v.w);
    }
#pragma unroll
    for (int o = 16; o; o >>= 1) s += __shfl_xor_sync(0xffffffffu, s, o);
    if (lane == 0) {
        int i = warp & (NN - 1);
        float dg = row[i];
        float rs = s - dg + 1.0f;
        g_deg[warp]  = rsqrtf(fmaxf(rs, 1.0f));
        g_diag[warp] = dg;
    }
}

// ---------------- kernel B: H' = tf32(diag(d) * (x @ [Wq|Wk|Wv])) ------------
__global__ void __launch_bounds__(320) h_kernel(const float* __restrict__ x,
                                                const float* __restrict__ Wq,
                                                const float* __restrict__ Wk,
                                                const float* __restrict__ Wv) {
    __shared__ float xs[64][IND];
    int b = blockIdx.y;
    int rb = blockIdx.x;
    int t = threadIdx.x;
    size_t rowbase = ((size_t)b * NN + rb * 64);

    for (int idx = t; idx < 64 * IND; idx += 320) {
        int r = idx >> 6, k = idx & 63;
        xs[r][k] = x[(rowbase + r) * IND + k];
    }
    __syncthreads();

    const float* Wcol;
    int stride;
    if (t < 128)      { Wcol = Wq + t;          stride = 128; }
    else if (t < 256) { Wcol = Wk + (t - 128);  stride = 128; }
    else              { Wcol = Wv + (t - 256);  stride = 64;  }

    float w[64];
#pragma unroll
    for (int k = 0; k < 64; k++) w[k] = Wcol[(size_t)k * stride];

    const float4* xs4 = (const float4*)&xs[0][0];
    for (int r = 0; r < 64; r++) {
        float acc = 0.f;
#pragma unroll
        for (int kq = 0; kq < 16; kq++) {
            float4 xv = xs4[r * 16 + kq];
            acc += xv.x * w[kq * 4 + 0];
            acc += xv.y * w[kq * 4 + 1];
            acc += xv.z * w[kq * 4 + 2];
            acc += xv.w * w[kq * 4 + 3];
        }
        g_H[(rowbase + r) * CTOT + t] = f2tf32f(g_deg[rowbase + r] * acc);
    }
}

// ---------------- kernel C: tf32 tensor-core GCN GEMM (R3 layout) -----------
// C = diag(d) * (adj_raw @ H' + (1-diag)*H'_row) + bias, routed to Q/K/V.
// CTA tile 128(M) x 64(N), K step 32. 8 warps in 4(m) x 2(n); warp = 32x32.
#define ASTRIDE 36
#define BSTRIDE 72

__global__ void __launch_bounds__(256) gcn_gemm_tc(const float* __restrict__ adj,
                                                   const float* __restrict__ bq,
                                                   const float* __restrict__ bk,
                                                   const float* __restrict__ bv,
                                                   float* __restrict__ outV) {
    __shared__ float As[128 * ASTRIDE];   // 18432 B
    __shared__ float Bs[32 * BSTRIDE];    //  9216 B

    int b  = blockIdx.z;
    int mt = blockIdx.y;     // 0..7 -> 128-row tiles
    int cb = blockIdx.x;     // 0..4 -> 64-col tiles of 320
    int t  = threadIdx.x;
    int wid = t >> 5, lane = t & 31;
    int g = lane >> 2, tg = lane & 3;
    int wm = wid >> 1, wn = wid & 1;

    const float* adjb = adj + (size_t)b * NN * NN + (size_t)(mt * 128) * NN;
    const float* Hb   = g_H + (size_t)b * NN * CTOT;
    int colbase = cb * 64;

    int ar[4], aq[4];
#pragma unroll
    for (int i = 0; i < 4; i++) { int lin = t + i * 256; ar[i] = lin >> 3; aq[i] = lin & 7; }
    int bkk[2], bq_[2];
#pragma unroll
    for (int i = 0; i < 2; i++) { int lin = t + i * 256; bkk[i] = lin >> 4; bq_[i] = lin & 15; }

    float4 pa[4], pb[2];
#define LOAD_PREF(K0)                                                              \
    {                                                                              \
        _Pragma("unroll")                                                          \
        for (int i = 0; i < 4; i++)                                                \
            pa[i] = *(const float4*)(adjb + (size_t)ar[i] * NN + (K0) + aq[i] * 4);\
        _Pragma("unroll")                                                          \
        for (int i = 0; i < 2; i++)                                                \
            pb[i] = *(const float4*)(Hb + (size_t)((K0) + bkk[i]) * CTOT + colbase + bq_[i] * 4); \
    }
#define STORE_SMEM()                                                               \
    {                                                                              \
        _Pragma("unroll")                                                          \
        for (int i = 0; i < 4; i++) {                                              \
            float4 v = pa[i];                                                      \
            v.x = f2tf32f(v.x); v.y = f2tf32f(v.y);                                \
            v.z = f2tf32f(v.z); v.w = f2tf32f(v.w);                                \
            *(float4*)&As[ar[i] * ASTRIDE + aq[i] * 4] = v;                        \
        }                                                                          \
        _Pragma("unroll")                                                          \
        for (int i = 0; i < 2; i++)                                                \
            *(float4*)&Bs[bkk[i] * BSTRIDE + bq_[i] * 4] = pb[i];                  \
    }

    float acc[2][4][4];
#pragma unroll
    for (int m = 0; m < 2; m++)
#pragma unroll
        for (int n = 0; n < 4; n++)
#pragma unroll
            for (int e = 0; e < 4; e++) acc[m][n][e] = 0.f;

    LOAD_PREF(0);
    STORE_SMEM();

    for (int k0 = 0; k0 < NN; k0 += 32) {
        __syncthreads();
        if (k0 + 32 < NN) LOAD_PREF(k0 + 32);

#pragma unroll
        for (int ks = 0; ks < 4; ks++) {
            int kb = ks * 8;
            uint32_t a[2][4];
#pragma unroll
            for (int m = 0; m < 2; m++) {
                int rb = wm * 32 + m * 16;
                a[m][0] = __float_as_uint(As[(rb + g)     * ASTRIDE + kb + tg]);
                a[m][1] = __float_as_uint(As[(rb + g + 8) * ASTRIDE + kb + tg]);
                a[m][2] = __float_as_uint(As[(rb + g)     * ASTRIDE + kb + tg + 4]);
                a[m][3] = __float_as_uint(As[(rb + g + 8) * ASTRIDE + kb + tg + 4]);
            }
#pragma unroll
            for (int n = 0; n < 4; n++) {
                int cc = wn * 32 + n * 8 + g;
                uint32_t b0 = __float_as_uint(Bs[(kb + tg)     * BSTRIDE + cc]);
                uint32_t b1 = __float_as_uint(Bs[(kb + tg + 4) * BSTRIDE + cc]);
#pragma unroll
                for (int m = 0; m < 2; m++)
                    mma_tf32(acc[m][n], a[m][0], a[m][1], a[m][2], a[m][3], b0, b1);
            }
        }
        __syncthreads();
        if (k0 + 32 < NN) STORE_SMEM();
    }

    // epilogue: route to g_Q / g_K / outV; round Q/K to tf32 for the attn pass
    float* dst; const float* barr; int jb, stride; bool roundout;
    if (cb < 2)      { dst = g_Q + (size_t)b * NN * ATTN;  barr = bq; jb = cb * 64;       stride = ATTN; roundout = true; }
    else if (cb < 4) { dst = g_K + (size_t)b * NN * ATTN;  barr = bk; jb = (cb - 2) * 64; stride = ATTN; roundout = true; }
    else             { dst = outV + (size_t)b * NN * OUTD; barr = bv; jb = 0;             stride = OUTD; roundout = false; }

#pragma unroll
    for (int m = 0; m < 2; m++) {
        int r0 = mt * 128 + wm * 32 + m * 16 + g;
#pragma unroll
        for (int rr = 0; rr < 2; rr++) {
            int i = r0 + rr * 8;
            size_t gi = (size_t)b * NN + i;
            float d    = g_deg[gi];
            float corr = 1.0f - g_diag[gi];
#pragma unroll
            for (int n = 0; n < 4; n++) {
                int jl = jb + wn * 32 + n * 8 + 2 * tg;
                int jg = colbase + wn * 32 + n * 8 + 2 * tg;
                float2 h2 = *(const float2*)(Hb + (size_t)i * CTOT + jg);
                float v0 = d * (acc[m][n][rr * 2 + 0] + corr * h2.x) + barr[jl];
                float v1 = d * (acc[m][n][rr * 2 + 1] + corr * h2.y) + barr[jl + 1];
                if (roundout) { v0 = f2tf32f(v0); v1 = f2tf32f(v1); }
                float2 ov; ov.x = v0; ov.y = v1;
                *(float2*)(dst + (size_t)i * stride + jl) = ov;
            }
        }
    }
}

// ---------------- kernel D: tensor-core A = sym(mean_h tanh(Qh Khᵀ / 8)) ----
// K-chunked (2 chunks of 64) to shrink smem -> 4 CTAs/SM. C2 aliases Qs.
// Upper-tri compacted grid: 136 pair-blocks x 32 batches.
#define QS 68                  // 64 + 4 pad: bank = (4g+tg)%32 distinct
#define TS 65

// load 64x64 chunk (col offset c0) of a row-major [64 x ATTN] tile
__device__ __forceinline__ void load_chunk(float* dst, const float* __restrict__ src,
                                           int c0, int t) {
    for (int idx = t; idx < 64 * 16; idx += 256) {
        int r = idx >> 4, q = idx & 15;
        float4 v = *(const float4*)(src + r * ATTN + c0 + q * 4);
        *(float4*)(dst + r * QS + q * 4) = v;
    }
}

// accumulate 2 heads (k-chunk of 64) into out; tanh per head.
__device__ __forceinline__ void attn_chunk(const float* __restrict__ Qs,
                                           const float* __restrict__ Ks,
                                           int wm, int wn, int g, int tg,
                                           float out[4][4]) {
#pragma unroll
    for (int h = 0; h < 2; h++) {
        float acc[4][4];
#pragma unroll
        for (int n = 0; n < 4; n++)
#pragma unroll
            for (int e = 0; e < 4; e++) acc[n][e] = 0.f;

#pragma unroll
        for (int ks = 0; ks < 4; ks++) {
            int kb = h * 32 + ks * 8;
            int rb = wm * 16;
            uint32_t a0 = __float_as_uint(Qs[(rb + g)     * QS + kb + tg]);
            uint32_t a1 = __float_as_uint(Qs[(rb + g + 8) * QS + kb + tg]);
            uint32_t a2 = __float_as_uint(Qs[(rb + g)     * QS + kb + tg + 4]);
            uint32_t a3 = __float_as_uint(Qs[(rb + g + 8) * QS + kb + tg + 4]);
#pragma unroll
            for (int n = 0; n < 4; n++) {
                int cc = wn * 32 + n * 8 + g;
                uint32_t b0 = __float_as_uint(Ks[cc * QS + kb + tg]);
                uint32_t b1 = __float_as_uint(Ks[cc * QS + kb + tg + 4]);
                mma_tf32(acc[n], a0, a1, a2, a3, b0, b1);
            }
        }
#pragma unroll
        for (int n = 0; n < 4; n++)
#pragma unroll
            for (int e = 0; e < 4; e++)
                out[n][e] += fast_tanh(acc[n][e] * 0.125f);
    }
}

// compute full raw tile (rows of tileR x cols of tileC), chunked over k
__device__ __forceinline__ void compute_tile_chunked(float* Qs, float* Ks,
                                                     const float* qsrc,
                                                     const float* ksrc,
                                                     int wm, int wn, int g, int tg,
                                                     int t, float out[4][4]) {
#pragma unroll
    for (int n = 0; n < 4; n++)
#pragma unroll
        for (int e = 0; e < 4; e++) out[n][e] = 0.f;
#pragma unroll
    for (int c = 0; c < 2; c++) {
        load_chunk(Qs, qsrc, c * 64, t);
        load_chunk(Ks, ksrc, c * 64, t);
        __syncthreads();
        attn_chunk(Qs, Ks, wm, wn, g, tg, out);
        __syncthreads();
    }
#pragma unroll
    for (int n = 0; n < 4; n++)
#pragma unroll
        for (int e = 0; e < 4; e++) out[n][e] *= 0.25f;   // head mean
}

#define SMEM_D ((2 * 64 * QS + 64 * TS) * (int)sizeof(float))  // 51,456 B

__global__ void __launch_bounds__(256, 4) attn_tc(float* __restrict__ outA) {
    extern __shared__ float sm[];
    float* Qs = sm;                    // 64*68
    float* Ks = sm + 64 * QS;          // 64*68
    float* T1 = sm + 2 * 64 * QS;      // 64*65
    float* C2 = Qs;                    // alias: Qs dead after last MMA

    // upper-triangular pair decode
    int p = blockIdx.x, b = blockIdx.y;
    int I = 0;
    while (p >= 16 - I) { p -= 16 - I; I++; }
    int J = I + p;

    int t = threadIdx.x;
    int wid = t >> 5, lane = t & 31;
    int g = lane >> 2, tg = lane & 3;
    int wm = wid >> 1, wn = wid & 1;

    const float* qI = g_Q + ((size_t)b * NN + I * 64) * ATTN;
    const float* kJ = g_K + ((size_t)b * NN + J * 64) * ATTN;

    float o1[4][4];
    compute_tile_chunked(Qs, Ks, qI, kJ, wm, wn, g, tg, t, o1);  // raw (I,J)
#pragma unroll
    for (int n = 0; n < 4; n++)
#pragma unroll
        for (int e = 0; e < 4; e++) {
            int r = wm * 16 + g + (e >> 1) * 8;
            int c = wn * 32 + n * 8 + 2 * tg + (e & 1);
            T1[r * TS + c] = o1[n][e];
        }
    __syncthreads();

    if (I == J) {
        for (int idx = t; idx < 4096; idx += 256) {
            int r = idx >> 6, c = idx & 63;
            C2[r * TS + c] = 0.5f * (T1[r * TS + c] + T1[c * TS + r]);
        }
        __syncthreads();
    } else {
        const float* qJ = g_Q + ((size_t)b * NN + J * 64) * ATTN;
        const float* kI = g_K + ((size_t)b * NN + I * 64) * ATTN;
        float o2[4][4];
        compute_tile_chunked(Qs, Ks, qJ, kI, wm, wn, g, tg, t, o2);  // raw (J,I)
        // (compute_tile_chunked ends with __syncthreads: Qs free -> C2 safe)
#pragma unroll
        for (int n = 0; n < 4; n++)
#pragma unroll
            for (int e = 0; e < 4; e++) {
                int r = wm * 16 + g + (e >> 1) * 8;
                int c = wn * 32 + n * 8 + 2 * tg + (e & 1);
                C2[r * TS + c] = 0.5f * (o2[n][e] + T1[c * TS + r]);
            }
        __syncthreads();
    }

    // C2 holds output tile (J,I): scalar LDS reads, packed STG.128 writes.
    float* ob = outA + ((size_t)b * NN + J * 64) * NN + I * 64;
    for (int idx = t; idx < 1024; idx += 256) {
        int r = idx >> 4, cq = idx & 15;
        const float* row = &C2[r * TS + cq * 4];
        float4 v;
        v.x = row[0]; v.y = row[1]; v.z = row[2]; v.w = row[3];
        *(float4*)(ob + (size_t)r * NN + cq * 4) = v;
    }
    if (I != J) {
        float* ob2 = outA + ((size_t)b * NN + I * 64) * NN + J * 64;
        for (int idx = t; idx < 1024; idx += 256) {
            int r = idx >> 4, cq = idx & 15;
            float4 v;
            v.x = C2[(cq * 4 + 0) * TS + r];
            v.y = C2[(cq * 4 + 1) * TS + r];
            v.z = C2[(cq * 4 + 2) * TS + r];
            v.w = C2[(cq * 4 + 3) * TS + r];
            *(float4*)(ob2 + (size_t)r * NN + cq * 4) = v;
        }
    }
}

// ---------------- launch -----------------------------------------------------
extern "C" void kernel_launch(void* const* d_in, const int* in_sizes, int n_in,
                              void* d_out, int out_size) {
    (void)in_sizes; (void)n_in; (void)out_size;
    const float* x   = (const float*)d_in[0];
    const float* adj = (const float*)d_in[1];
    // d_in[2] = flags (unused by reference)
    const float* Wq = (const float*)d_in[3];
    const float* bq = (const float*)d_in[4];
    const float* Wk = (const float*)d_in[5];
    const float* bk = (const float*)d_in[6];
    const float* Wv = (const float*)d_in[7];
    const float* bv = (const float*)d_in[8];

    float* outV = (float*)d_out;                            // [B,N,64]
    float* outA = (float*)d_out + (size_t)BB * NN * OUTD;   // [B,N,N]

    cudaFuncSetAttribute(attn_tc,
                         cudaFuncAttributeMaxDynamicSharedMemorySize, SMEM_D);

    deg_kernel<<<(BB * NN) / 8, 256>>>(adj);
    h_kernel<<<dim3(16, BB), 320>>>(x, Wq, Wk, Wv);
    gcn_gemm_tc<<<dim3(5, 8, BB), 256>>>(adj, bq, bk, bv, outV);
    attn_tc<<<dim3(136, BB), 256, SMEM_D>>>(outA);
}